// round 1
// baseline (speedup 1.0000x reference)
#include <cuda_runtime.h>
#include <math.h>

#define T 4096
#define H 1024
#define E 8
#define I 1024
#define NSLOT (T * 2)

#define BM 64
#define BN 64
#define BK 16

// ---------------- scratch (device globals; no allocations allowed) ----------
__device__ int   g_cnt[E];
__device__ int   g_tok[E * T];      // token id per (expert, pos)
__device__ int   g_dest[E * T];     // dest row = t*2 + slot
__device__ float g_cw[NSLOT];       // combine weight per (t, slot)
__device__ float g_h[(size_t)NSLOT * I];   // GLU output rows (t*2+slot, I)
__device__ float g_y[(size_t)NSLOT * H];   // expert output rows (t*2+slot, H)

// ---------------- kernel 0: zero counters -----------------------------------
__global__ void k_zero() {
    if (threadIdx.x < E) g_cnt[threadIdx.x] = 0;
}

// ---------------- kernel 1: routing ------------------------------------------
__global__ void k_route(const float* __restrict__ logits,
                        const float* __restrict__ pes) {
    int t = blockIdx.x * blockDim.x + threadIdx.x;
    if (t >= T) return;

    float l[E];
    const float4* lp = (const float4*)(logits + (size_t)t * E);
    float4 a = lp[0], b = lp[1];
    l[0] = a.x; l[1] = a.y; l[2] = a.z; l[3] = a.w;
    l[4] = b.x; l[5] = b.y; l[6] = b.z; l[7] = b.w;

    float mx = l[0];
#pragma unroll
    for (int i = 1; i < E; i++) mx = fmaxf(mx, l[i]);
    float p[E], s = 0.f;
#pragma unroll
    for (int i = 0; i < E; i++) { p[i] = __expf(l[i] - mx); s += p[i]; }
    float inv = 1.f / s;
#pragma unroll
    for (int i = 0; i < E; i++) p[i] *= inv;

    // top-2 on logits (== top-2 on probs), first-index tie break like jax
    int e0 = 0;
#pragma unroll
    for (int i = 1; i < E; i++) if (l[i] > l[e0]) e0 = i;
    int e1 = (e0 == 0) ? 1 : 0;
#pragma unroll
    for (int i = 0; i < E; i++) if (i != e0 && l[i] > l[e1]) e1 = i;

    float denom = p[e0] + p[e1];
    float w0 = p[e0] / denom * pes[e0];
    float w1 = p[e1] / denom * pes[e1];

    int pos0 = atomicAdd(&g_cnt[e0], 1);
    g_tok[e0 * T + pos0]  = t;
    g_dest[e0 * T + pos0] = 2 * t;
    g_cw[2 * t] = w0;

    int pos1 = atomicAdd(&g_cnt[e1], 1);
    g_tok[e1 * T + pos1]  = t;
    g_dest[e1 * T + pos1] = 2 * t + 1;
    g_cw[2 * t + 1] = w1;
}

// ---------------- kernel 2: GEMM1 (x @ w1^T, x @ w3^T) + GELU*u -> h ---------
// grid: (T/BM, I/BN, E), block: 256
__global__ __launch_bounds__(256) void k_gemm1(const float* __restrict__ x,
                                               const float* __restrict__ w13) {
    const int e = blockIdx.z;
    const int cnt = g_cnt[e];
    const int row0 = blockIdx.x * BM;
    if (row0 >= cnt) return;
    const int col0 = blockIdx.y * BN;

    __shared__ float As[BK][BM + 1];
    __shared__ float B1s[BK][BN + 1];
    __shared__ float B3s[BK][BN + 1];
    __shared__ int   toks[BM];
    __shared__ int   dests[BM];

    const int tid = threadIdx.x;
    if (tid < BM) {
        int r = row0 + tid;
        toks[tid]  = (r < cnt) ? g_tok[e * T + r]  : 0;
        dests[tid] = (r < cnt) ? g_dest[e * T + r] : 0;
    }
    __syncthreads();

    const int lm = tid >> 2;          // 0..63
    const int lk = (tid & 3) * 4;     // 0,4,8,12
    const int tx = tid & 15;          // col group
    const int ty = tid >> 4;          // row group

    float accG[4][4] = {}, accU[4][4] = {};

    const float* b1base = w13 + ((size_t)e * 2 * I + col0 + lm) * H;
    const float* b3base = w13 + ((size_t)e * 2 * I + I + col0 + lm) * H;
    const float* arow   = x + (size_t)toks[lm] * H;

    for (int k0 = 0; k0 < H; k0 += BK) {
        float4 av = *(const float4*)(arow + k0 + lk);
        float4 b1 = *(const float4*)(b1base + k0 + lk);
        float4 b3 = *(const float4*)(b3base + k0 + lk);
        As[lk + 0][lm] = av.x; As[lk + 1][lm] = av.y;
        As[lk + 2][lm] = av.z; As[lk + 3][lm] = av.w;
        B1s[lk + 0][lm] = b1.x; B1s[lk + 1][lm] = b1.y;
        B1s[lk + 2][lm] = b1.z; B1s[lk + 3][lm] = b1.w;
        B3s[lk + 0][lm] = b3.x; B3s[lk + 1][lm] = b3.y;
        B3s[lk + 2][lm] = b3.z; B3s[lk + 3][lm] = b3.w;
        __syncthreads();

#pragma unroll
        for (int k = 0; k < BK; k++) {
            float a[4], c1[4], c3[4];
#pragma unroll
            for (int i = 0; i < 4; i++) a[i] = As[k][ty * 4 + i];
#pragma unroll
            for (int j = 0; j < 4; j++) { c1[j] = B1s[k][tx * 4 + j]; c3[j] = B3s[k][tx * 4 + j]; }
#pragma unroll
            for (int i = 0; i < 4; i++)
#pragma unroll
                for (int j = 0; j < 4; j++) {
                    accG[i][j] = fmaf(a[i], c1[j], accG[i][j]);
                    accU[i][j] = fmaf(a[i], c3[j], accU[i][j]);
                }
        }
        __syncthreads();
    }

#pragma unroll
    for (int i = 0; i < 4; i++) {
        int m = ty * 4 + i;
        if (row0 + m < cnt) {
            float* hrow = g_h + (size_t)dests[m] * I + col0;
#pragma unroll
            for (int j = 0; j < 4; j++) {
                float g = accG[i][j], u = accU[i][j];
                float ge = 0.5f * g * (1.f + erff(g * 0.7071067811865475f));
                hrow[tx * 4 + j] = ge * u;
            }
        }
    }
}

// ---------------- kernel 3: GEMM2 (h @ w2^T) -> y ----------------------------
// grid: (T/BM, H/BN, E), block: 256
__global__ __launch_bounds__(256) void k_gemm2(const float* __restrict__ w2) {
    const int e = blockIdx.z;
    const int cnt = g_cnt[e];
    const int row0 = blockIdx.x * BM;
    if (row0 >= cnt) return;
    const int col0 = blockIdx.y * BN;

    __shared__ float As[BK][BM + 1];
    __shared__ float Bs[BK][BN + 1];
    __shared__ int   dests[BM];

    const int tid = threadIdx.x;
    if (tid < BM) {
        int r = row0 + tid;
        dests[tid] = (r < cnt) ? g_dest[e * T + r] : 0;
    }
    __syncthreads();

    const int lm = tid >> 2;
    const int lk = (tid & 3) * 4;
    const int tx = tid & 15;
    const int ty = tid >> 4;

    float acc[4][4] = {};

    const float* arow  = g_h + (size_t)dests[lm] * I;
    const float* bbase = w2 + ((size_t)e * H + col0 + lm) * I;

    for (int k0 = 0; k0 < I; k0 += BK) {
        float4 av = *(const float4*)(arow + k0 + lk);
        float4 bv = *(const float4*)(bbase + k0 + lk);
        As[lk + 0][lm] = av.x; As[lk + 1][lm] = av.y;
        As[lk + 2][lm] = av.z; As[lk + 3][lm] = av.w;
        Bs[lk + 0][lm] = bv.x; Bs[lk + 1][lm] = bv.y;
        Bs[lk + 2][lm] = bv.z; Bs[lk + 3][lm] = bv.w;
        __syncthreads();

#pragma unroll
        for (int k = 0; k < BK; k++) {
            float a[4], b[4];
#pragma unroll
            for (int i = 0; i < 4; i++) a[i] = As[k][ty * 4 + i];
#pragma unroll
            for (int j = 0; j < 4; j++) b[j] = Bs[k][tx * 4 + j];
#pragma unroll
            for (int i = 0; i < 4; i++)
#pragma unroll
                for (int j = 0; j < 4; j++)
                    acc[i][j] = fmaf(a[i], b[j], acc[i][j]);
        }
        __syncthreads();
    }

#pragma unroll
    for (int i = 0; i < 4; i++) {
        int m = ty * 4 + i;
        if (row0 + m < cnt) {
            float* yrow = g_y + (size_t)dests[m] * H + col0;
#pragma unroll
            for (int j = 0; j < 4; j++) yrow[tx * 4 + j] = acc[i][j];
        }
    }
}

// ---------------- kernel 4: combine ------------------------------------------
__global__ void k_combine(float* __restrict__ out) {
    int idx = blockIdx.x * blockDim.x + threadIdx.x;   // over T * H/4
    if (idx >= T * (H / 4)) return;
    int t  = idx / (H / 4);
    int c4 = idx % (H / 4);
    float w0 = g_cw[2 * t], w1 = g_cw[2 * t + 1];
    const float4* y0 = (const float4*)(g_y + (size_t)(2 * t) * H) + c4;
    const float4* y1 = (const float4*)(g_y + (size_t)(2 * t + 1) * H) + c4;
    float4 a = *y0, b = *y1, o;
    o.x = w0 * a.x + w1 * b.x;
    o.y = w0 * a.y + w1 * b.y;
    o.z = w0 * a.z + w1 * b.z;
    o.w = w0 * a.w + w1 * b.w;
    ((float4*)out)[idx] = o;
}

// ---------------- launch ------------------------------------------------------
extern "C" void kernel_launch(void* const* d_in, const int* in_sizes, int n_in,
                              void* d_out, int out_size) {
    const float* x      = (const float*)d_in[0];
    const float* logits = (const float*)d_in[1];
    const float* pes    = (const float*)d_in[2];
    const float* w13    = (const float*)d_in[3];
    const float* w2     = (const float*)d_in[4];
    float* out = (float*)d_out;

    k_zero<<<1, 32>>>();
    k_route<<<(T + 255) / 256, 256>>>(logits, pes);
    k_gemm1<<<dim3(T / BM, I / BN, E), 256>>>(x, w13);
    k_gemm2<<<dim3(T / BM, H / BN, E), 256>>>(w2);
    k_combine<<<(T * (H / 4) + 255) / 256, 256>>>(out);
}

// round 4
// speedup vs baseline: 1.8338x; 1.8338x over previous
#include <cuda_runtime.h>
#include <math.h>

#define T 4096
#define H 1024
#define E 8
#define I 1024
#define NSLOT (T * 2)

#define BM1 128
#define BN1 64
#define BK1 16
#define APITCH 136   // (128+8): 8-word skew per k-row -> conflict-free frag loads
#define BPITCH 72    // (64+8)

// ---------------- scratch (device globals; no allocations allowed) ----------
__device__ int   g_cnt[E];
__device__ int   g_tok[E * T];
__device__ int   g_dest[E * T];
__device__ float g_cw[NSLOT];
__device__ float g_h[(size_t)NSLOT * I];
__device__ float g_y[(size_t)NSLOT * H];

// ---------------- helpers -----------------------------------------------------
__device__ __forceinline__ unsigned f2tf(float f) {
    unsigned u;
    asm("cvt.rna.tf32.f32 %0, %1;" : "=r"(u) : "f"(f));
    return u;
}

__device__ __forceinline__ void mma_tf32(float (&c)[4], const unsigned (&a)[4],
                                         unsigned b0, unsigned b1) {
    asm volatile(
        "mma.sync.aligned.m16n8k8.row.col.f32.tf32.tf32.f32 "
        "{%0,%1,%2,%3},{%4,%5,%6,%7},{%8,%9},{%0,%1,%2,%3};"
        : "+f"(c[0]), "+f"(c[1]), "+f"(c[2]), "+f"(c[3])
        : "r"(a[0]), "r"(a[1]), "r"(a[2]), "r"(a[3]), "r"(b0), "r"(b1));
}

__device__ __forceinline__ float gelu_exact(float g) {
    return 0.5f * g * (1.f + erff(g * 0.7071067811865475f));
}

// ---------------- kernel 0: zero counters -----------------------------------
__global__ void k_zero() {
    if (threadIdx.x < E) g_cnt[threadIdx.x] = 0;
}

// ---------------- kernel 1: routing ------------------------------------------
__global__ void k_route(const float* __restrict__ logits,
                        const float* __restrict__ pes) {
    int t = blockIdx.x * blockDim.x + threadIdx.x;
    if (t >= T) return;

    float l[E];
    const float4* lp = (const float4*)(logits + (size_t)t * E);
    float4 a = lp[0], b = lp[1];
    l[0] = a.x; l[1] = a.y; l[2] = a.z; l[3] = a.w;
    l[4] = b.x; l[5] = b.y; l[6] = b.z; l[7] = b.w;

    float mx = l[0];
#pragma unroll
    for (int i = 1; i < E; i++) mx = fmaxf(mx, l[i]);
    float p[E], s = 0.f;
#pragma unroll
    for (int i = 0; i < E; i++) { p[i] = __expf(l[i] - mx); s += p[i]; }
    float inv = 1.f / s;
#pragma unroll
    for (int i = 0; i < E; i++) p[i] *= inv;

    int e0 = 0;
#pragma unroll
    for (int i = 1; i < E; i++) if (l[i] > l[e0]) e0 = i;
    int e1 = (e0 == 0) ? 1 : 0;
#pragma unroll
    for (int i = 0; i < E; i++) if (i != e0 && l[i] > l[e1]) e1 = i;

    float denom = p[e0] + p[e1];
    float w0 = p[e0] / denom * pes[e0];
    float w1 = p[e1] / denom * pes[e1];

    int pos0 = atomicAdd(&g_cnt[e0], 1);
    g_tok[e0 * T + pos0]  = t;
    g_dest[e0 * T + pos0] = 2 * t;
    g_cw[2 * t] = w0;

    int pos1 = atomicAdd(&g_cnt[e1], 1);
    g_tok[e1 * T + pos1]  = t;
    g_dest[e1 * T + pos1] = 2 * t + 1;
    g_cw[2 * t + 1] = w1;
}

// ---------------- kernel 2: GEMM1 tf32 mma: g,u then GELU(g)*u -> h ----------
// grid: (T/BM1, I/BN1, E), block 256 (8 warps as 4M x 2N)
__global__ __launch_bounds__(256) void k_gemm1(const float* __restrict__ x,
                                               const float* __restrict__ w13) {
    const int e = blockIdx.z;
    const int cnt = g_cnt[e];
    const int row0 = blockIdx.x * BM1;
    if (row0 >= cnt) return;
    const int col0 = blockIdx.y * BN1;

    __shared__ unsigned As[2][BK1][APITCH];
    __shared__ unsigned B1s[2][BK1][BPITCH];
    __shared__ unsigned B3s[2][BK1][BPITCH];
    __shared__ int toks[BM1], dests[BM1];

    const int tid = threadIdx.x;
    if (tid < BM1) {
        int r = row0 + tid;
        toks[tid]  = (r < cnt) ? g_tok[e * T + r]  : 0;
        dests[tid] = (r < cnt) ? g_dest[e * T + r] : 0;
    }
    __syncthreads();

    // loader mapping
    const int am  = tid & 127;        // A row within tile
    const int akg = tid >> 7;         // 0/1 -> k-groups {akg*4, akg*4+8}
    const int bn  = tid & 63;         // B row (n) within tile
    const int bkg = tid >> 6;         // 0..3 -> k offset bkg*4

    const float* arow   = x + (size_t)toks[am] * H;
    const float* b1base = w13 + ((size_t)e * 2 * I + col0 + bn) * H;
    const float* b3base = b1base + (size_t)I * H;

    // prologue: fill buffer 0 (k0 = 0)
    {
        float4 a0 = *(const float4*)(arow + akg * 4);
        float4 a1 = *(const float4*)(arow + akg * 4 + 8);
        float4 v1 = *(const float4*)(b1base + bkg * 4);
        float4 v3 = *(const float4*)(b3base + bkg * 4);
        int ka = akg * 4;
        As[0][ka + 0][am] = f2tf(a0.x); As[0][ka + 1][am] = f2tf(a0.y);
        As[0][ka + 2][am] = f2tf(a0.z); As[0][ka + 3][am] = f2tf(a0.w);
        As[0][ka + 8][am] = f2tf(a1.x); As[0][ka + 9][am] = f2tf(a1.y);
        As[0][ka + 10][am] = f2tf(a1.z); As[0][ka + 11][am] = f2tf(a1.w);
        int kb = bkg * 4;
        B1s[0][kb + 0][bn] = f2tf(v1.x); B1s[0][kb + 1][bn] = f2tf(v1.y);
        B1s[0][kb + 2][bn] = f2tf(v1.z); B1s[0][kb + 3][bn] = f2tf(v1.w);
        B3s[0][kb + 0][bn] = f2tf(v3.x); B3s[0][kb + 1][bn] = f2tf(v3.y);
        B3s[0][kb + 2][bn] = f2tf(v3.z); B3s[0][kb + 3][bn] = f2tf(v3.w);
    }
    __syncthreads();

    const int lane = tid & 31;
    const int w    = tid >> 5;
    const int wm   = w & 3;           // 0..3  (M groups of 32)
    const int wn   = w >> 2;          // 0..1  (N groups of 32)
    const int grp  = lane >> 2;       // 0..7
    const int tig  = lane & 3;        // 0..3

    float accG[2][4][4] = {}, accU[2][4][4] = {};

    int cur = 0;
    for (int k0 = 0; k0 < H; k0 += BK1) {
        const bool more = (k0 + BK1) < H;
        float4 ra0, ra1, rv1, rv3;
        if (more) {
            ra0 = *(const float4*)(arow + k0 + BK1 + akg * 4);
            ra1 = *(const float4*)(arow + k0 + BK1 + akg * 4 + 8);
            rv1 = *(const float4*)(b1base + k0 + BK1 + bkg * 4);
            rv3 = *(const float4*)(b3base + k0 + BK1 + bkg * 4);
        }

#pragma unroll
        for (int ks = 0; ks < 2; ks++) {
            const int kb = ks * 8;
            unsigned a[2][4];
#pragma unroll
            for (int mi = 0; mi < 2; mi++) {
                int r = wm * 32 + mi * 16 + grp;
                a[mi][0] = As[cur][kb + tig][r];
                a[mi][1] = As[cur][kb + tig][r + 8];
                a[mi][2] = As[cur][kb + 4 + tig][r];
                a[mi][3] = As[cur][kb + 4 + tig][r + 8];
            }
#pragma unroll
            for (int ni = 0; ni < 4; ni++) {
                int c = wn * 32 + ni * 8 + grp;
                unsigned b10 = B1s[cur][kb + tig][c];
                unsigned b11 = B1s[cur][kb + 4 + tig][c];
                unsigned b30 = B3s[cur][kb + tig][c];
                unsigned b31 = B3s[cur][kb + 4 + tig][c];
#pragma unroll
                for (int mi = 0; mi < 2; mi++) {
                    mma_tf32(accG[mi][ni], a[mi], b10, b11);
                    mma_tf32(accU[mi][ni], a[mi], b30, b31);
                }
            }
        }

        if (more) {
            int nxt = cur ^ 1;
            int ka = akg * 4;
            As[nxt][ka + 0][am] = f2tf(ra0.x); As[nxt][ka + 1][am] = f2tf(ra0.y);
            As[nxt][ka + 2][am] = f2tf(ra0.z); As[nxt][ka + 3][am] = f2tf(ra0.w);
            As[nxt][ka + 8][am] = f2tf(ra1.x); As[nxt][ka + 9][am] = f2tf(ra1.y);
            As[nxt][ka + 10][am] = f2tf(ra1.z); As[nxt][ka + 11][am] = f2tf(ra1.w);
            int kb2 = bkg * 4;
            B1s[nxt][kb2 + 0][bn] = f2tf(rv1.x); B1s[nxt][kb2 + 1][bn] = f2tf(rv1.y);
            B1s[nxt][kb2 + 2][bn] = f2tf(rv1.z); B1s[nxt][kb2 + 3][bn] = f2tf(rv1.w);
            B3s[nxt][kb2 + 0][bn] = f2tf(rv3.x); B3s[nxt][kb2 + 1][bn] = f2tf(rv3.y);
            B3s[nxt][kb2 + 2][bn] = f2tf(rv3.z); B3s[nxt][kb2 + 3][bn] = f2tf(rv3.w);
            __syncthreads();
            cur = nxt;
        }
    }

    // epilogue: GELU(g)*u scattered to g_h
#pragma unroll
    for (int mi = 0; mi < 2; mi++) {
#pragma unroll
        for (int half = 0; half < 2; half++) {
            int mrow = wm * 32 + mi * 16 + grp + half * 8;
            if (row0 + mrow < cnt) {
                float* hrow = g_h + (size_t)dests[mrow] * I + col0 + wn * 32;
#pragma unroll
                for (int ni = 0; ni < 4; ni++) {
                    float gA = accG[mi][ni][half * 2 + 0];
                    float gB = accG[mi][ni][half * 2 + 1];
                    float uA = accU[mi][ni][half * 2 + 0];
                    float uB = accU[mi][ni][half * 2 + 1];
                    hrow[ni * 8 + tig * 2 + 0] = gelu_exact(gA) * uA;
                    hrow[ni * 8 + tig * 2 + 1] = gelu_exact(gB) * uB;
                }
            }
        }
    }
}

// ---------------- kernel 3: GEMM2 tf32 mma: h @ w2^T -> y --------------------
// grid: (T/BM1, H/BN1, E), block 256
__global__ __launch_bounds__(256) void k_gemm2(const float* __restrict__ w2) {
    const int e = blockIdx.z;
    const int cnt = g_cnt[e];
    const int row0 = blockIdx.x * BM1;
    if (row0 >= cnt) return;
    const int col0 = blockIdx.y * BN1;

    __shared__ unsigned As[2][BK1][APITCH];
    __shared__ unsigned Bs[2][BK1][BPITCH];
    __shared__ int dests[BM1];

    const int tid = threadIdx.x;
    if (tid < BM1) {
        int r = row0 + tid;
        dests[tid] = (r < cnt) ? g_dest[e * T + r] : 0;
    }
    __syncthreads();

    const int am  = tid & 127;
    const int akg = tid >> 7;
    const int bn  = tid & 63;
    const int bkg = tid >> 6;

    const float* arow  = g_h + (size_t)dests[am] * I;
    const float* bbase = w2 + ((size_t)e * H + col0 + bn) * I;

    {
        float4 a0 = *(const float4*)(arow + akg * 4);
        float4 a1 = *(const float4*)(arow + akg * 4 + 8);
        float4 bv = *(const float4*)(bbase + bkg * 4);
        int ka = akg * 4;
        As[0][ka + 0][am] = f2tf(a0.x); As[0][ka + 1][am] = f2tf(a0.y);
        As[0][ka + 2][am] = f2tf(a0.z); As[0][ka + 3][am] = f2tf(a0.w);
        As[0][ka + 8][am] = f2tf(a1.x); As[0][ka + 9][am] = f2tf(a1.y);
        As[0][ka + 10][am] = f2tf(a1.z); As[0][ka + 11][am] = f2tf(a1.w);
        int kb = bkg * 4;
        Bs[0][kb + 0][bn] = f2tf(bv.x); Bs[0][kb + 1][bn] = f2tf(bv.y);
        Bs[0][kb + 2][bn] = f2tf(bv.z); Bs[0][kb + 3][bn] = f2tf(bv.w);
    }
    __syncthreads();

    const int lane = tid & 31;
    const int w    = tid >> 5;
    const int wm   = w & 3;
    const int wn   = w >> 2;
    const int grp  = lane >> 2;
    const int tig  = lane & 3;

    float acc[2][4][4] = {};

    int cur = 0;
    for (int k0 = 0; k0 < I; k0 += BK1) {
        const bool more = (k0 + BK1) < I;
        float4 ra0, ra1, rbv;
        if (more) {
            ra0 = *(const float4*)(arow + k0 + BK1 + akg * 4);
            ra1 = *(const float4*)(arow + k0 + BK1 + akg * 4 + 8);
            rbv = *(const float4*)(bbase + k0 + BK1 + bkg * 4);
        }

#pragma unroll
        for (int ks = 0; ks < 2; ks++) {
            const int kb = ks * 8;
            unsigned a[2][4];
#pragma unroll
            for (int mi = 0; mi < 2; mi++) {
                int r = wm * 32 + mi * 16 + grp;
                a[mi][0] = As[cur][kb + tig][r];
                a[mi][1] = As[cur][kb + tig][r + 8];
                a[mi][2] = As[cur][kb + 4 + tig][r];
                a[mi][3] = As[cur][kb + 4 + tig][r + 8];
            }
#pragma unroll
            for (int ni = 0; ni < 4; ni++) {
                int c = wn * 32 + ni * 8 + grp;
                unsigned b0 = Bs[cur][kb + tig][c];
                unsigned b1 = Bs[cur][kb + 4 + tig][c];
#pragma unroll
                for (int mi = 0; mi < 2; mi++)
                    mma_tf32(acc[mi][ni], a[mi], b0, b1);
            }
        }

        if (more) {
            int nxt = cur ^ 1;
            int ka = akg * 4;
            As[nxt][ka + 0][am] = f2tf(ra0.x); As[nxt][ka + 1][am] = f2tf(ra0.y);
            As[nxt][ka + 2][am] = f2tf(ra0.z); As[nxt][ka + 3][am] = f2tf(ra0.w);
            As[nxt][ka + 8][am] = f2tf(ra1.x); As[nxt][ka + 9][am] = f2tf(ra1.y);
            As[nxt][ka + 10][am] = f2tf(ra1.z); As[nxt][ka + 11][am] = f2tf(ra1.w);
            int kb2 = bkg * 4;
            Bs[nxt][kb2 + 0][bn] = f2tf(rbv.x); Bs[nxt][kb2 + 1][bn] = f2tf(rbv.y);
            Bs[nxt][kb2 + 2][bn] = f2tf(rbv.z); Bs[nxt][kb2 + 3][bn] = f2tf(rbv.w);
            __syncthreads();
            cur = nxt;
        }
    }

#pragma unroll
    for (int mi = 0; mi < 2; mi++) {
#pragma unroll
        for (int half = 0; half < 2; half++) {
            int mrow = wm * 32 + mi * 16 + grp + half * 8;
            if (row0 + mrow < cnt) {
                float* yrow = g_y + (size_t)dests[mrow] * H + col0 + wn * 32;
#pragma unroll
                for (int ni = 0; ni < 4; ni++) {
                    yrow[ni * 8 + tig * 2 + 0] = acc[mi][ni][half * 2 + 0];
                    yrow[ni * 8 + tig * 2 + 1] = acc[mi][ni][half * 2 + 1];
                }
            }
        }
    }
}

// ---------------- kernel 4: combine ------------------------------------------
__global__ void k_combine(float* __restrict__ out) {
    int idx = blockIdx.x * blockDim.x + threadIdx.x;
    if (idx >= T * (H / 4)) return;
    int t  = idx / (H / 4);
    int c4 = idx % (H / 4);
    float w0 = g_cw[2 * t], w1 = g_cw[2 * t + 1];
    const float4* y0 = (const float4*)(g_y + (size_t)(2 * t) * H) + c4;
    const float4* y1 = (const float4*)(g_y + (size_t)(2 * t + 1) * H) + c4;
    float4 a = *y0, b = *y1, o;
    o.x = w0 * a.x + w1 * b.x;
    o.y = w0 * a.y + w1 * b.y;
    o.z = w0 * a.z + w1 * b.z;
    o.w = w0 * a.w + w1 * b.w;
    ((float4*)out)[idx] = o;
}

// ---------------- launch ------------------------------------------------------
extern "C" void kernel_launch(void* const* d_in, const int* in_sizes, int n_in,
                              void* d_out, int out_size) {
    const float* x      = (const float*)d_in[0];
    const float* logits = (const float*)d_in[1];
    const float* pes    = (const float*)d_in[2];
    const float* w13    = (const float*)d_in[3];
    const float* w2     = (const float*)d_in[4];
    float* out = (float*)d_out;

    k_zero<<<1, 32>>>();
    k_route<<<(T + 255) / 256, 256>>>(logits, pes);
    k_gemm1<<<dim3(T / BM1, I / BN1, E), 256>>>(x, w13);
    k_gemm2<<<dim3(T / BM1, H / BN1, E), 256>>>(w2);
    k_combine<<<(T * (H / 4) + 255) / 256, 256>>>(out);
}